// round 12
// baseline (speedup 1.0000x reference)
#include <cuda_runtime.h>
#include <cuda_fp16.h>
#include <cstdint>

#define D_MODEL 1024
#define NHEAD   16
#define HDIM    64
#define BATCH   2
#define SEQ     2048
#define MROWS   (BATCH*SEQ)       // 4096
#define QKVDIM  (3*D_MODEL)       // 3072

// Scratch (no cudaMalloc allowed)
__device__ __half g_qkvh [BATCH*SEQ*QKVDIM];   // 25 MB
__device__ __half g_attnh[BATCH*SEQ*D_MODEL];  //  8 MB

// ---------------------------------------------------------------------------
// helpers
// ---------------------------------------------------------------------------
static __device__ __forceinline__ uint32_t smem_u32(const void* p) {
    uint32_t a;
    asm("{ .reg .u64 t; cvta.to.shared.u64 t, %1; cvt.u32.u64 %0, t; }"
        : "=r"(a) : "l"(p));
    return a;
}
static __device__ __forceinline__ void mma16(
    float& c0, float& c1, float& c2, float& c3,
    uint32_t a0, uint32_t a1, uint32_t a2, uint32_t a3,
    uint32_t b0, uint32_t b1)
{
    asm volatile(
        "mma.sync.aligned.m16n8k16.row.col.f32.f16.f16.f32 "
        "{%0,%1,%2,%3}, {%4,%5,%6,%7}, {%8,%9}, {%0,%1,%2,%3};"
        : "+f"(c0), "+f"(c1), "+f"(c2), "+f"(c3)
        : "r"(a0), "r"(a1), "r"(a2), "r"(a3), "r"(b0), "r"(b1));
}
static __device__ __forceinline__ void ldmx4(
    uint32_t& r0, uint32_t& r1, uint32_t& r2, uint32_t& r3, uint32_t addr)
{
    asm volatile("ldmatrix.sync.aligned.m8n8.x4.shared.b16 {%0,%1,%2,%3}, [%4];"
                 : "=r"(r0), "=r"(r1), "=r"(r2), "=r"(r3) : "r"(addr));
}
static __device__ __forceinline__ void ldmx4t(
    uint32_t& r0, uint32_t& r1, uint32_t& r2, uint32_t& r3, uint32_t addr)
{
    asm volatile("ldmatrix.sync.aligned.m8n8.x4.trans.shared.b16 {%0,%1,%2,%3}, [%4];"
                 : "=r"(r0), "=r"(r1), "=r"(r2), "=r"(r3) : "r"(addr));
}
static __device__ __forceinline__ void cpa16(uint32_t dst, const void* src) {
    asm volatile("cp.async.ca.shared.global [%0], [%1], 16;"
                 :: "r"(dst), "l"(src) : "memory");
}
static __device__ __forceinline__ void cpa_commit() {
    asm volatile("cp.async.commit_group;" ::: "memory");
}
static __device__ __forceinline__ void cpa_wait0() {
    asm volatile("cp.async.wait_group 0;" ::: "memory");
}
static __device__ __forceinline__ void st2h(__half* C, size_t off, float a, float b) {
    *(__half2*)(C + off) = __floats2half2_rn(a, b);
}
static __device__ __forceinline__ void st2h(float* C, size_t off, float a, float b) {
    *(float2*)(C + off) = make_float2(a, b);
}
static __device__ __forceinline__ uint32_t packh2(float a, float b) {
    __half2 h = __floats2half2_rn(a, b);
    return *(uint32_t*)&h;
}

// 32 contiguous elements -> 4 x uint4 of packed halves (convert if f32 src)
static __device__ __forceinline__ void load_conv(const float* __restrict__ src,
                                                 uint4 out[4]) {
    #pragma unroll
    for (int i = 0; i < 4; i++) {
        float4 lo = ((const float4*)src)[2 * i];
        float4 hi = ((const float4*)src)[2 * i + 1];
        out[i] = make_uint4(packh2(lo.x, lo.y), packh2(lo.z, lo.w),
                            packh2(hi.x, hi.y), packh2(hi.z, hi.w));
    }
}
static __device__ __forceinline__ void load_conv(const __half* __restrict__ src,
                                                 uint4 out[4]) {
    #pragma unroll
    for (int i = 0; i < 4; i++) out[i] = ((const uint4*)src)[i];
}

// ===========================================================================
// fp16 mma GEMM (TN) with in-kernel f32->f16 conversion of inputs:
//   C[m][n] = sum_k A[m*K+k]*B[n*K+k], fp32 accumulate.
// CTA 128x128, BK=64 halves (128B rows, chunk-swizzle c^(row&7)).
// 256 thr, 8 warps (2m x 4n), warp tile 64x32. Register double-buffer
// (load next k-slab to regs during compute; STS between two syncs).
// ===========================================================================
#define HSTAGE    32768          // A 16KB + B 16KB (f16)
#define GEMM_SMEM (2*HSTAGE)     // 65536

template<typename AT, typename BT, typename OutT>
__global__ void __launch_bounds__(256) gemm_f16c(
    const AT* __restrict__ A, const BT* __restrict__ B,
    OutT* __restrict__ C, int M, int N, int K, int q_cols, float qs)
{
    extern __shared__ char smh[];
    const uint32_t sbase = smem_u32(smh);

    const int tid  = threadIdx.x;
    const int wid  = tid >> 5;
    const int lane = tid & 31;
    const int g    = lane >> 2;
    const int ct   = lane & 3;
    const int wm   = wid & 1;
    const int wn   = wid >> 1;
    const int bm   = blockIdx.y * 128;
    const int bn   = blockIdx.x * 128;
    const float osc = (bn < q_cols) ? qs : 1.0f;

    const int l8 = lane & 7;
    const int h1 = (lane >> 3) & 1;
    const int h2 = lane >> 4;

    uint32_t arow[4], a7[4], brow[2], b7[2];
    #pragma unroll
    for (int mi = 0; mi < 4; mi++) {
        int r = wm * 64 + mi * 16 + l8 + h1 * 8;
        arow[mi] = (uint32_t)(r * 128);
        a7[mi]   = (uint32_t)(r & 7);
    }
    #pragma unroll
    for (int p = 0; p < 2; p++) {
        int r = wn * 32 + p * 16 + l8 + h2 * 8;
        brow[p] = 16384u + (uint32_t)(r * 128);
        b7[p]   = (uint32_t)(r & 7);
    }

    // gmem mapping: row = tid>>1, 32-element half-slab at (tid&1)*32
    const int crow = tid >> 1;
    const int chalf = tid & 1;
    const AT* Ag = A + (size_t)(bm + crow) * K + chalf * 32;
    const BT* Bg = B + (size_t)(bn + crow) * K + chalf * 32;
    uint32_t dwa[4], dwb[4];
    #pragma unroll
    for (int i = 0; i < 4; i++) {
        uint32_t sw = (uint32_t)(((chalf * 4 + i) ^ (crow & 7)) * 16);
        dwa[i] = (uint32_t)(crow * 128) + sw;
        dwb[i] = 16384u + (uint32_t)(crow * 128) + sw;
    }

    const int nkt = K / 64;

    float acc[4][4][4];
    #pragma unroll
    for (int i = 0; i < 4; i++)
        #pragma unroll
        for (int j = 0; j < 4; j++)
            #pragma unroll
            for (int e = 0; e < 4; e++) acc[i][j][e] = 0.f;

    // prologue: tile 0 -> regs -> stage 0
    uint4 ra[4], rb[4];
    load_conv(Ag, ra);
    load_conv(Bg, rb);
    #pragma unroll
    for (int i = 0; i < 4; i++) {
        *(uint4*)(smh + dwa[i]) = ra[i];
        *(uint4*)(smh + dwb[i]) = rb[i];
    }
    __syncthreads();

    for (int kt = 0; kt < nkt; kt++) {
        if (kt + 1 < nkt) {
            load_conv(Ag + (kt + 1) * 64, ra);
            load_conv(Bg + (kt + 1) * 64, rb);
        }

        const uint32_t cbase = sbase + (uint32_t)(kt & 1) * HSTAGE;
        #pragma unroll
        for (int ks = 0; ks < 4; ks++) {
            uint32_t a[4][4], bb[2][4];
            #pragma unroll
            for (int mi = 0; mi < 4; mi++)
                ldmx4(a[mi][0], a[mi][1], a[mi][2], a[mi][3],
                      cbase + arow[mi] + ((((uint32_t)(ks * 2 + h2)) ^ a7[mi]) << 4));
            #pragma unroll
            for (int p = 0; p < 2; p++)
                ldmx4(bb[p][0], bb[p][1], bb[p][2], bb[p][3],
                      cbase + brow[p] + ((((uint32_t)(ks * 2 + h1)) ^ b7[p]) << 4));
            #pragma unroll
            for (int mi = 0; mi < 4; mi++)
                #pragma unroll
                for (int nt = 0; nt < 4; nt++)
                    mma16(acc[mi][nt][0], acc[mi][nt][1], acc[mi][nt][2], acc[mi][nt][3],
                          a[mi][0], a[mi][1], a[mi][2], a[mi][3],
                          bb[nt >> 1][(nt & 1) * 2], bb[nt >> 1][(nt & 1) * 2 + 1]);
        }

        if (kt + 1 < nkt) {
            __syncthreads();   // all warps done reading the buffer being overwritten
            char* st = smh + ((kt + 1) & 1) * HSTAGE;
            #pragma unroll
            for (int i = 0; i < 4; i++) {
                *(uint4*)(st + dwa[i]) = ra[i];
                *(uint4*)(st + dwb[i]) = rb[i];
            }
            __syncthreads();
        }
    }

    #pragma unroll
    for (int mi = 0; mi < 4; mi++) {
        int r0 = bm + wm * 64 + mi * 16 + g;
        #pragma unroll
        for (int nt = 0; nt < 4; nt++) {
            int c0 = bn + wn * 32 + nt * 8 + 2 * ct;
            st2h(C, (size_t)r0 * N + c0,
                 acc[mi][nt][0] * osc, acc[mi][nt][1] * osc);
            st2h(C, (size_t)(r0 + 8) * N + c0,
                 acc[mi][nt][2] * osc, acc[mi][nt][3] * osc);
        }
    }
}

// ===========================================================================
// Flash attention, fp16 mma, P in registers (FA2), exp2-domain softmax.
// Unchanged from round 11.
// ===========================================================================
#define AQ_OFF 0
#define AK_OFF 16384
#define AV_OFF 32768
#define ATTN_SMEM 49152

__global__ void __launch_bounds__(256, 2) attn_f16(
    const __half* __restrict__ qkv, __half* __restrict__ attn_out)
{
    extern __shared__ char smh[];
    const uint32_t sb = smem_u32(smh);

    const int qt  = (int)gridDim.x - 1 - (int)blockIdx.x;  // heavy blocks first
    const int h   = blockIdx.y;
    const int b   = blockIdx.z;
    const int tid = threadIdx.x;
    const int wid = tid >> 5;
    const int lane = tid & 31;
    const int g   = lane >> 2;
    const int ct  = lane & 3;
    const int q0  = qt * 128;
    const int rl  = wid * 16 + g;

    const int l8 = lane & 7;
    const int h1 = (lane >> 3) & 1;
    const int h2 = lane >> 4;

    const int arow = wid * 16 + l8 + h1 * 8;
    const uint32_t qbase = sb + AQ_OFF + (uint32_t)(arow * 128);
    const uint32_t a7 = (uint32_t)(arow & 7);
    uint32_t krow[4], k7[4];
    #pragma unroll
    for (int p = 0; p < 4; p++) {
        int r = p * 16 + l8 + h2 * 8;
        krow[p] = (uint32_t)(r * 128);
        k7[p]   = (uint32_t)(r & 7);
    }
    const int vr0 = l8 + h1 * 8;

    const size_t rs = QKVDIM;
    const __half* Qg = qkv + (size_t)b * SEQ * rs + h * HDIM;
    const __half* Kg = Qg + D_MODEL;
    const __half* Vg = Qg + 2 * D_MODEL;

    const int krr0 = tid >> 3;
    const int kc   = tid & 7;
    const uint32_t ksw0 = (uint32_t)(krr0 * 128 + ((kc ^ (krr0 & 7)) * 16));
    const int krr1 = krr0 + 32;
    const uint32_t ksw1 = (uint32_t)(krr1 * 128 + ((kc ^ (krr1 & 7)) * 16));

    // load Q tile (once)
    #pragma unroll
    for (int it = 0; it < 4; it++) {
        int idx = tid + it * 256;
        int rr  = idx >> 3;
        int c   = idx & 7;
        uint4 v = *(const uint4*)(Qg + (size_t)(q0 + rr) * rs + c * 8);
        *(uint4*)(smh + AQ_OFF + rr * 128 + ((c ^ (rr & 7)) * 16)) = v;
    }

    const int nkt = 2 * qt + 2;

    // prologue: kt=0 K/V into stage 0
    cpa16(sb + AK_OFF + ksw0, Kg + (size_t)krr0 * rs + kc * 8);
    cpa16(sb + AK_OFF + ksw1, Kg + (size_t)krr1 * rs + kc * 8);
    cpa16(sb + AV_OFF + ksw0, Vg + (size_t)krr0 * rs + kc * 8);
    cpa16(sb + AV_OFF + ksw1, Vg + (size_t)krr1 * rs + kc * 8);
    cpa_commit();

    float m_lo = -1e30f, m_hi = -1e30f, l_lo = 0.f, l_hi = 0.f;
    float o[8][4];
    #pragma unroll
    for (int nt = 0; nt < 8; nt++)
        #pragma unroll
        for (int e = 0; e < 4; e++) o[nt][e] = 0.f;

    for (int kt = 0; kt < nkt; kt++) {
        cpa_wait0();
        __syncthreads();

        if (kt + 1 < nkt) {
            const int k1 = (kt + 1) * 64;
            const uint32_t so = (uint32_t)((kt + 1) & 1) * 8192u;
            cpa16(sb + AK_OFF + so + ksw0, Kg + (size_t)(k1 + krr0) * rs + kc * 8);
            cpa16(sb + AK_OFF + so + ksw1, Kg + (size_t)(k1 + krr1) * rs + kc * 8);
            cpa16(sb + AV_OFF + so + ksw0, Vg + (size_t)(k1 + krr0) * rs + kc * 8);
            cpa16(sb + AV_OFF + so + ksw1, Vg + (size_t)(k1 + krr1) * rs + kc * 8);
            cpa_commit();
        }

        const int k0 = kt * 64;
        if (k0 > q0 + wid * 16 + 15) continue;

        const uint32_t kb = sb + AK_OFF + (uint32_t)(kt & 1) * 8192u;
        const uint32_t vb = sb + AV_OFF + (uint32_t)(kt & 1) * 8192u;

        // ---- S = Q K^T (S in log2 units) ----
        float s[8][4];
        #pragma unroll
        for (int nt = 0; nt < 8; nt++)
            #pragma unroll
            for (int e = 0; e < 4; e++) s[nt][e] = 0.f;

        #pragma unroll
        for (int ks = 0; ks < 4; ks++) {
            uint32_t a0, a1, a2, a3;
            ldmx4(a0, a1, a2, a3, qbase + ((((uint32_t)(ks * 2 + h2)) ^ a7) << 4));
            #pragma unroll
            for (int p = 0; p < 4; p++) {
                uint32_t b0, b1, b2, b3;
                ldmx4(b0, b1, b2, b3, kb + krow[p] + ((((uint32_t)(ks * 2 + h1)) ^ k7[p]) << 4));
                mma16(s[2*p][0], s[2*p][1], s[2*p][2], s[2*p][3],
                      a0, a1, a2, a3, b0, b1);
                mma16(s[2*p+1][0], s[2*p+1][1], s[2*p+1][2], s[2*p+1][3],
                      a0, a1, a2, a3, b2, b3);
            }
        }

        // ---- causal mask ----
        const int rglo = q0 + rl;
        const int rghi = rglo + 8;
        if (k0 + 63 > rglo) {
            #pragma unroll
            for (int nt = 0; nt < 8; nt++) {
                int key = k0 + nt * 8 + 2 * ct;
                if (key     > rglo) s[nt][0] = -1e30f;
                if (key + 1 > rglo) s[nt][1] = -1e30f;
                if (key     > rghi) s[nt][2] = -1e30f;
                if (key + 1 > rghi) s[nt][3] = -1e30f;
            }
        }

        // ---- online softmax (base 2) ----
        float tlo = -1e30f, thi = -1e30f;
        #pragma unroll
        for (int nt = 0; nt < 8; nt++) {
            tlo = fmaxf(tlo, fmaxf(s[nt][0], s[nt][1]));
            thi = fmaxf(thi, fmaxf(s[nt][2], s[nt][3]));
        }
        tlo = fmaxf(tlo, __shfl_xor_sync(0xffffffffu, tlo, 1));
        tlo = fmaxf(tlo, __shfl_xor_sync(0xffffffffu, tlo, 2));
        thi = fmaxf(thi, __shfl_xor_sync(0xffffffffu, thi, 1));
        thi = fmaxf(thi, __shfl_xor_sync(0xffffffffu, thi, 2));

        float mn_lo = fmaxf(m_lo, tlo);
        float mn_hi = fmaxf(m_hi, thi);
        float al_lo = exp2f(m_lo - mn_lo);
        float al_hi = exp2f(m_hi - mn_hi);
        m_lo = mn_lo; m_hi = mn_hi;

        uint32_t plo[8], phi[8];
        float ps_lo = 0.f, ps_hi = 0.f;
        #pragma unroll
        for (int nt = 0; nt < 8; nt++) {
            float p0 = exp2f(s[nt][0] - mn_lo);
            float p1 = exp2f(s[nt][1] - mn_lo);
            float p2 = exp2f(s[nt][2] - mn_hi);
            float p3 = exp2f(s[nt][3] - mn_hi);
            ps_lo += p0 + p1;
            ps_hi += p2 + p3;
            plo[nt] = packh2(p0, p1);
            phi[nt] = packh2(p2, p3);
        }
        l_lo = l_lo * al_lo + ps_lo;
        l_hi = l_hi * al_hi + ps_hi;

        #pragma unroll
        for (int nt = 0; nt < 8; nt++) {
            o[nt][0] *= al_lo; o[nt][1] *= al_lo;
            o[nt][2] *= al_hi; o[nt][3] *= al_hi;
        }

        // ---- O += P V ----
        #pragma unroll
        for (int ks = 0; ks < 4; ks++) {
            uint32_t a0 = plo[2*ks], a1 = phi[2*ks];
            uint32_t a2 = plo[2*ks+1], a3 = phi[2*ks+1];
            int vrow = ks * 16 + vr0;
            uint32_t vbase = vb + (uint32_t)(vrow * 128);
            uint32_t v7 = (uint32_t)(vrow & 7);
            #pragma unroll
            for (int pn = 0; pn < 4; pn++) {
                uint32_t b0, b1, b2, b3;
                ldmx4t(b0, b1, b2, b3, vbase + ((((uint32_t)(pn * 2 + h2)) ^ v7) << 4));
                mma16(o[2*pn][0], o[2*pn][1], o[2*pn][2], o[2*pn][3],
                      a0, a1, a2, a3, b0, b1);
                mma16(o[2*pn+1][0], o[2*pn+1][1], o[2*pn+1][2], o[2*pn+1][3],
                      a0, a1, a2, a3, b2, b3);
            }
        }
    }

    l_lo += __shfl_xor_sync(0xffffffffu, l_lo, 1);
    l_lo += __shfl_xor_sync(0xffffffffu, l_lo, 2);
    l_hi += __shfl_xor_sync(0xffffffffu, l_hi, 1);
    l_hi += __shfl_xor_sync(0xffffffffu, l_hi, 2);
    float inv_lo = 1.0f / l_lo;
    float inv_hi = 1.0f / l_hi;

    __half* Og = attn_out + (size_t)(b * SEQ + q0) * D_MODEL + h * HDIM;
    #pragma unroll
    for (int nt = 0; nt < 8; nt++) {
        int col = nt * 8 + 2 * ct;
        *(__half2*)&Og[(size_t)rl * D_MODEL + col] =
            __floats2half2_rn(o[nt][0] * inv_lo, o[nt][1] * inv_lo);
        *(__half2*)&Og[(size_t)(rl + 8) * D_MODEL + col] =
            __floats2half2_rn(o[nt][2] * inv_hi, o[nt][3] * inv_hi);
    }
}

// ===========================================================================
extern "C" void kernel_launch(void* const* d_in, const int* in_sizes, int n_in,
                              void* d_out, int out_size)
{
    const float* x      = (const float*)d_in[0];
    const float* w_qkv  = (const float*)d_in[1];
    const float* w_proj = (const float*)d_in[2];
    float* out = (float*)d_out;

    __half *qkvh, *attnh;
    cudaGetSymbolAddress((void**)&qkvh,  g_qkvh);
    cudaGetSymbolAddress((void**)&attnh, g_attnh);

    cudaFuncSetAttribute((const void*)gemm_f16c<float, float, __half>,
                         cudaFuncAttributeMaxDynamicSharedMemorySize, GEMM_SMEM);
    cudaFuncSetAttribute((const void*)gemm_f16c<__half, float, float>,
                         cudaFuncAttributeMaxDynamicSharedMemorySize, GEMM_SMEM);
    cudaFuncSetAttribute(attn_f16,
                         cudaFuncAttributeMaxDynamicSharedMemorySize, ATTN_SMEM);

    // 1) QKV projection directly from f32 inputs; Q pre-scaled by (1/8)*log2(e)
    dim3 g1(QKVDIM/128, MROWS/128);
    gemm_f16c<float, float, __half><<<g1, 256, GEMM_SMEM>>>(
        x, w_qkv, qkvh, MROWS, QKVDIM, D_MODEL,
        D_MODEL, 0.125f * 1.44269504f);

    // 2) causal flash attention (P in registers, exp2 softmax)
    dim3 g2(SEQ/128, NHEAD, BATCH);
    attn_f16<<<g2, 256, ATTN_SMEM>>>(qkvh, attnh);

    // 3) output projection: f16 activations x f32 weights -> f32 out
    dim3 g3(D_MODEL/128, MROWS/128);
    gemm_f16c<__half, float, float><<<g3, 256, GEMM_SMEM>>>(
        attnh, w_proj, out, MROWS, D_MODEL, D_MODEL,
        0, 1.0f);
}

// round 14
// speedup vs baseline: 1.7236x; 1.7236x over previous
#include <cuda_runtime.h>
#include <cuda_fp16.h>
#include <cstdint>

#define D_MODEL 1024
#define NHEAD   16
#define HDIM    64
#define BATCH   2
#define SEQ     2048
#define MROWS   (BATCH*SEQ)       // 4096
#define QKVDIM  (3*D_MODEL)       // 3072

// Scratch (no cudaMalloc allowed)
__device__ __half g_qkvh [BATCH*SEQ*QKVDIM];   // 25 MB
__device__ __half g_attnh[BATCH*SEQ*D_MODEL];  //  8 MB
__device__ __half g_xh   [MROWS*D_MODEL];      //  8 MB
__device__ __half g_wqh  [QKVDIM*D_MODEL];     //  6 MB
__device__ __half g_wph  [D_MODEL*D_MODEL];    //  2 MB

// ---------------------------------------------------------------------------
// helpers
// ---------------------------------------------------------------------------
static __device__ __forceinline__ uint32_t smem_u32(const void* p) {
    uint32_t a;
    asm("{ .reg .u64 t; cvta.to.shared.u64 t, %1; cvt.u32.u64 %0, t; }"
        : "=r"(a) : "l"(p));
    return a;
}
static __device__ __forceinline__ void mma16(
    float& c0, float& c1, float& c2, float& c3,
    uint32_t a0, uint32_t a1, uint32_t a2, uint32_t a3,
    uint32_t b0, uint32_t b1)
{
    asm volatile(
        "mma.sync.aligned.m16n8k16.row.col.f32.f16.f16.f32 "
        "{%0,%1,%2,%3}, {%4,%5,%6,%7}, {%8,%9}, {%0,%1,%2,%3};"
        : "+f"(c0), "+f"(c1), "+f"(c2), "+f"(c3)
        : "r"(a0), "r"(a1), "r"(a2), "r"(a3), "r"(b0), "r"(b1));
}
static __device__ __forceinline__ void ldmx4(
    uint32_t& r0, uint32_t& r1, uint32_t& r2, uint32_t& r3, uint32_t addr)
{
    asm volatile("ldmatrix.sync.aligned.m8n8.x4.shared.b16 {%0,%1,%2,%3}, [%4];"
                 : "=r"(r0), "=r"(r1), "=r"(r2), "=r"(r3) : "r"(addr));
}
static __device__ __forceinline__ void ldmx4t(
    uint32_t& r0, uint32_t& r1, uint32_t& r2, uint32_t& r3, uint32_t addr)
{
    asm volatile("ldmatrix.sync.aligned.m8n8.x4.trans.shared.b16 {%0,%1,%2,%3}, [%4];"
                 : "=r"(r0), "=r"(r1), "=r"(r2), "=r"(r3) : "r"(addr));
}
static __device__ __forceinline__ void cpa16(uint32_t dst, const void* src) {
    asm volatile("cp.async.ca.shared.global [%0], [%1], 16;"
                 :: "r"(dst), "l"(src) : "memory");
}
static __device__ __forceinline__ void cpa_commit() {
    asm volatile("cp.async.commit_group;" ::: "memory");
}
static __device__ __forceinline__ void cpa_wait1() {
    asm volatile("cp.async.wait_group 1;" ::: "memory");
}
static __device__ __forceinline__ void cpa_wait0() {
    asm volatile("cp.async.wait_group 0;" ::: "memory");
}
static __device__ __forceinline__ void st2h(__half* C, size_t off, float a, float b) {
    *(__half2*)(C + off) = __floats2half2_rn(a, b);
}
static __device__ __forceinline__ void st2h(float* C, size_t off, float a, float b) {
    *(float2*)(C + off) = make_float2(a, b);
}
static __device__ __forceinline__ uint32_t packh2(float a, float b) {
    __half2 h = __floats2half2_rn(a, b);
    return *(uint32_t*)&h;
}

// ---------------------------------------------------------------------------
// single-launch f32 -> f16 conversion of x, w_qkv, w_proj
// ---------------------------------------------------------------------------
#define N4X (MROWS*D_MODEL/4)
#define N4Q (QKVDIM*D_MODEL/4)
#define N4P (D_MODEL*D_MODEL/4)
__global__ void __launch_bounds__(256) f2h_all(
    const float4* __restrict__ x, const float4* __restrict__ wq,
    const float4* __restrict__ wp,
    __half2* __restrict__ xh, __half2* __restrict__ wqh, __half2* __restrict__ wph)
{
    int i = blockIdx.x * 256 + threadIdx.x;
    const float4* src; __half2* dst; int j;
    if (i < N4X)                { src = x;  dst = xh;  j = i; }
    else if (i < N4X + N4Q)     { src = wq; dst = wqh; j = i - N4X; }
    else if (i < N4X + N4Q + N4P){ src = wp; dst = wph; j = i - N4X - N4Q; }
    else return;
    float4 v = src[j];
    dst[2 * j]     = __floats2half2_rn(v.x, v.y);
    dst[2 * j + 1] = __floats2half2_rn(v.z, v.w);
}

// ===========================================================================
// fp16 mma GEMM (TN): C[m][n] = sum_k A[m*K+k]*B[n*K+k], fp32 accumulate.
// CTA 128x128, BK=64 halves (128B rows, chunk-swizzle c^(row&7)).
// 256 thr, 8 warps (2m x 4n), warp tile 64x32. 3-stage cp.async with the
// R11 ordering: wait_group 1 -> __syncthreads -> (issue kt+2) -> compute.
// ===========================================================================
#define HSTAGE    32768
#define GEMM_SMEM (3*HSTAGE)

template<typename OutT>
__global__ void __launch_bounds__(256, 2) gemm_f16(
    const __half* __restrict__ A, const __half* __restrict__ B,
    OutT* __restrict__ C, int M, int N, int K, int q_cols, float qs)
{
    extern __shared__ char smh[];
    const uint32_t sbase = smem_u32(smh);

    const int tid  = threadIdx.x;
    const int wid  = tid >> 5;
    const int lane = tid & 31;
    const int g    = lane >> 2;
    const int ct   = lane & 3;
    const int wm   = wid & 1;
    const int wn   = wid >> 1;
    const int bm   = blockIdx.y * 128;
    const int bn   = blockIdx.x * 128;
    const float osc = (bn < q_cols) ? qs : 1.0f;

    const int l8 = lane & 7;
    const int h1 = (lane >> 3) & 1;
    const int h2 = lane >> 4;

    uint32_t arow[4], a7[4], brow[2], b7[2];
    #pragma unroll
    for (int mi = 0; mi < 4; mi++) {
        int r = wm * 64 + mi * 16 + l8 + h1 * 8;
        arow[mi] = (uint32_t)(r * 128);
        a7[mi]   = (uint32_t)(r & 7);
    }
    #pragma unroll
    for (int p = 0; p < 2; p++) {
        int r = wn * 32 + p * 16 + l8 + h2 * 8;
        brow[p] = 16384u + (uint32_t)(r * 128);
        b7[p]   = (uint32_t)(r & 7);
    }

    const int crow = tid >> 1;
    const int cc0  = (tid & 1) * 4;
    const __half* Ag = A + (size_t)(bm + crow) * K;
    const __half* Bg = B + (size_t)(bn + crow) * K;
    uint32_t dwa[4], dwb[4];
    #pragma unroll
    for (int i = 0; i < 4; i++) {
        uint32_t sw = (uint32_t)(((cc0 + i) ^ (crow & 7)) * 16);
        dwa[i] = (uint32_t)(crow * 128) + sw;
        dwb[i] = 16384u + (uint32_t)(crow * 128) + sw;
    }

    const int nkt = K / 64;

    float acc[4][4][4];
    #pragma unroll
    for (int i = 0; i < 4; i++)
        #pragma unroll
        for (int j = 0; j < 4; j++)
            #pragma unroll
            for (int e = 0; e < 4; e++) acc[i][j][e] = 0.f;

    // prologue: stages 0,1
    #pragma unroll
    for (int s = 0; s < 2; s++) {
        uint32_t st = sbase + (uint32_t)s * HSTAGE;
        #pragma unroll
        for (int i = 0; i < 4; i++) {
            cpa16(st + dwa[i], Ag + s * 64 + (cc0 + i) * 8);
            cpa16(st + dwb[i], Bg + s * 64 + (cc0 + i) * 8);
        }
        cpa_commit();
    }

    int sc = 0;
    for (int kt = 0; kt < nkt; kt++) {
        cpa_wait1();       // stage sc complete (own groups)
        __syncthreads();   // cross-thread visibility + readers of old stage done

        if (kt + 2 < nkt) {
            int sn = sc + 2; if (sn >= 3) sn -= 3;
            uint32_t st = sbase + (uint32_t)sn * HSTAGE;
            #pragma unroll
            for (int i = 0; i < 4; i++) {
                cpa16(st + dwa[i], Ag + (kt + 2) * 64 + (cc0 + i) * 8);
                cpa16(st + dwb[i], Bg + (kt + 2) * 64 + (cc0 + i) * 8);
            }
        }
        cpa_commit();      // uniform group counting (possibly empty)

        const uint32_t cbase = sbase + (uint32_t)sc * HSTAGE;
        #pragma unroll
        for (int ks = 0; ks < 4; ks++) {
            uint32_t a[4][4], bb[2][4];
            #pragma unroll
            for (int mi = 0; mi < 4; mi++)
                ldmx4(a[mi][0], a[mi][1], a[mi][2], a[mi][3],
                      cbase + arow[mi] + ((((uint32_t)(ks * 2 + h2)) ^ a7[mi]) << 4));
            #pragma unroll
            for (int p = 0; p < 2; p++)
                ldmx4(bb[p][0], bb[p][1], bb[p][2], bb[p][3],
                      cbase + brow[p] + ((((uint32_t)(ks * 2 + h1)) ^ b7[p]) << 4));
            #pragma unroll
            for (int mi = 0; mi < 4; mi++)
                #pragma unroll
                for (int nt = 0; nt < 4; nt++)
                    mma16(acc[mi][nt][0], acc[mi][nt][1], acc[mi][nt][2], acc[mi][nt][3],
                          a[mi][0], a[mi][1], a[mi][2], a[mi][3],
                          bb[nt >> 1][(nt & 1) * 2], bb[nt >> 1][(nt & 1) * 2 + 1]);
        }
        sc++; if (sc >= 3) sc -= 3;
    }

    #pragma unroll
    for (int mi = 0; mi < 4; mi++) {
        int r0 = bm + wm * 64 + mi * 16 + g;
        #pragma unroll
        for (int nt = 0; nt < 4; nt++) {
            int c0 = bn + wn * 32 + nt * 8 + 2 * ct;
            st2h(C, (size_t)r0 * N + c0,
                 acc[mi][nt][0] * osc, acc[mi][nt][1] * osc);
            st2h(C, (size_t)(r0 + 8) * N + c0,
                 acc[mi][nt][2] * osc, acc[mi][nt][3] * osc);
        }
    }
}

// ===========================================================================
// Flash attention, fp16 mma, P in registers (FA2), exp2-domain softmax,
// 2-stage cp.async K/V pipeline with the R11 ordering:
// wait_group 0 -> __syncthreads -> issue kt+1 -> compute.
// Q pre-scaled by 0.125*log2(e) in the QKV GEMM epilogue.
// smem: Q 16K | K 2x8K | V 2x8K = 48K -> 2 CTAs/SM.
// ===========================================================================
#define AQ_OFF 0
#define AK_OFF 16384
#define AV_OFF 32768
#define ATTN_SMEM 49152

__global__ void __launch_bounds__(256, 2) attn_f16(
    const __half* __restrict__ qkv, __half* __restrict__ attn_out)
{
    extern __shared__ char smh[];
    const uint32_t sb = smem_u32(smh);

    const int qt  = (int)gridDim.x - 1 - (int)blockIdx.x;  // heavy blocks first
    const int h   = blockIdx.y;
    const int b   = blockIdx.z;
    const int tid = threadIdx.x;
    const int wid = tid >> 5;
    const int lane = tid & 31;
    const int g   = lane >> 2;
    const int ct  = lane & 3;
    const int q0  = qt * 128;
    const int rl  = wid * 16 + g;

    const int l8 = lane & 7;
    const int h1 = (lane >> 3) & 1;
    const int h2 = lane >> 4;

    const int arow = wid * 16 + l8 + h1 * 8;
    const uint32_t qbase = sb + AQ_OFF + (uint32_t)(arow * 128);
    const uint32_t a7 = (uint32_t)(arow & 7);
    uint32_t krow[4], k7[4];
    #pragma unroll
    for (int p = 0; p < 4; p++) {
        int r = p * 16 + l8 + h2 * 8;
        krow[p] = (uint32_t)(r * 128);
        k7[p]   = (uint32_t)(r & 7);
    }
    const int vr0 = l8 + h1 * 8;

    const size_t rs = QKVDIM;
    const __half* Qg = qkv + (size_t)b * SEQ * rs + h * HDIM;
    const __half* Kg = Qg + D_MODEL;
    const __half* Vg = Qg + 2 * D_MODEL;

    const int krr0 = tid >> 3;
    const int kc   = tid & 7;
    const uint32_t ksw0 = (uint32_t)(krr0 * 128 + ((kc ^ (krr0 & 7)) * 16));
    const int krr1 = krr0 + 32;
    const uint32_t ksw1 = (uint32_t)(krr1 * 128 + ((kc ^ (krr1 & 7)) * 16));

    // load Q tile (once)
    #pragma unroll
    for (int it = 0; it < 4; it++) {
        int idx = tid + it * 256;
        int rr  = idx >> 3;
        int c   = idx & 7;
        uint4 v = *(const uint4*)(Qg + (size_t)(q0 + rr) * rs + c * 8);
        *(uint4*)(smh + AQ_OFF + rr * 128 + ((c ^ (rr & 7)) * 16)) = v;
    }

    const int nkt = 2 * qt + 2;

    // prologue: kt=0 K/V into stage 0
    cpa16(sb + AK_OFF + ksw0, Kg + (size_t)krr0 * rs + kc * 8);
    cpa16(sb + AK_OFF + ksw1, Kg + (size_t)krr1 * rs + kc * 8);
    cpa16(sb + AV_OFF + ksw0, Vg + (size_t)krr0 * rs + kc * 8);
    cpa16(sb + AV_OFF + ksw1, Vg + (size_t)krr1 * rs + kc * 8);
    cpa_commit();

    float m_lo = -1e30f, m_hi = -1e30f, l_lo = 0.f, l_hi = 0.f;
    float o[8][4];
    #pragma unroll
    for (int nt = 0; nt < 8; nt++)
        #pragma unroll
        for (int e = 0; e < 4; e++) o[nt][e] = 0.f;

    for (int kt = 0; kt < nkt; kt++) {
        cpa_wait0();       // own groups complete (stage kt&1 data landed)
        __syncthreads();   // cross-thread visibility + old-stage readers done

        if (kt + 1 < nkt) {
            const int k1 = (kt + 1) * 64;
            const uint32_t so = (uint32_t)((kt + 1) & 1) * 8192u;
            cpa16(sb + AK_OFF + so + ksw0, Kg + (size_t)(k1 + krr0) * rs + kc * 8);
            cpa16(sb + AK_OFF + so + ksw1, Kg + (size_t)(k1 + krr1) * rs + kc * 8);
            cpa16(sb + AV_OFF + so + ksw0, Vg + (size_t)(k1 + krr0) * rs + kc * 8);
            cpa16(sb + AV_OFF + so + ksw1, Vg + (size_t)(k1 + krr1) * rs + kc * 8);
            cpa_commit();
        }

        const int k0 = kt * 64;
        if (k0 > q0 + wid * 16 + 15) continue;   // fully above diagonal

        const uint32_t kb = sb + AK_OFF + (uint32_t)(kt & 1) * 8192u;
        const uint32_t vb = sb + AV_OFF + (uint32_t)(kt & 1) * 8192u;

        // ---- S = Q K^T (S in log2 units) ----
        float s[8][4];
        #pragma unroll
        for (int nt = 0; nt < 8; nt++)
            #pragma unroll
            for (int e = 0; e < 4; e++) s[nt][e] = 0.f;

        #pragma unroll
        for (int ks = 0; ks < 4; ks++) {
            uint32_t a0, a1, a2, a3;
            ldmx4(a0, a1, a2, a3, qbase + ((((uint32_t)(ks * 2 + h2)) ^ a7) << 4));
            #pragma unroll
            for (int p = 0; p < 4; p++) {
                uint32_t b0, b1, b2, b3;
                ldmx4(b0, b1, b2, b3, kb + krow[p] + ((((uint32_t)(ks * 2 + h1)) ^ k7[p]) << 4));
                mma16(s[2*p][0], s[2*p][1], s[2*p][2], s[2*p][3],
                      a0, a1, a2, a3, b0, b1);
                mma16(s[2*p+1][0], s[2*p+1][1], s[2*p+1][2], s[2*p+1][3],
                      a0, a1, a2, a3, b2, b3);
            }
        }

        // ---- causal mask ----
        const int rglo = q0 + rl;
        const int rghi = rglo + 8;
        if (k0 + 63 > rglo) {
            #pragma unroll
            for (int nt = 0; nt < 8; nt++) {
                int key = k0 + nt * 8 + 2 * ct;
                if (key     > rglo) s[nt][0] = -1e30f;
                if (key + 1 > rglo) s[nt][1] = -1e30f;
                if (key     > rghi) s[nt][2] = -1e30f;
                if (key + 1 > rghi) s[nt][3] = -1e30f;
            }
        }

        // ---- online softmax (base 2; quad reduce for m) ----
        float tlo = -1e30f, thi = -1e30f;
        #pragma unroll
        for (int nt = 0; nt < 8; nt++) {
            tlo = fmaxf(tlo, fmaxf(s[nt][0], s[nt][1]));
            thi = fmaxf(thi, fmaxf(s[nt][2], s[nt][3]));
        }
        tlo = fmaxf(tlo, __shfl_xor_sync(0xffffffffu, tlo, 1));
        tlo = fmaxf(tlo, __shfl_xor_sync(0xffffffffu, tlo, 2));
        thi = fmaxf(thi, __shfl_xor_sync(0xffffffffu, thi, 1));
        thi = fmaxf(thi, __shfl_xor_sync(0xffffffffu, thi, 2));

        float mn_lo = fmaxf(m_lo, tlo);
        float mn_hi = fmaxf(m_hi, thi);
        float al_lo = exp2f(m_lo - mn_lo);
        float al_hi = exp2f(m_hi - mn_hi);
        m_lo = mn_lo; m_hi = mn_hi;

        uint32_t plo[8], phi[8];
        float ps_lo = 0.f, ps_hi = 0.f;
        #pragma unroll
        for (int nt = 0; nt < 8; nt++) {
            float p0 = exp2f(s[nt][0] - mn_lo);
            float p1 = exp2f(s[nt][1] - mn_lo);
            float p2 = exp2f(s[nt][2] - mn_hi);
            float p3 = exp2f(s[nt][3] - mn_hi);
            ps_lo += p0 + p1;
            ps_hi += p2 + p3;
            plo[nt] = packh2(p0, p1);
            phi[nt] = packh2(p2, p3);
        }
        l_lo = l_lo * al_lo + ps_lo;
        l_hi = l_hi * al_hi + ps_hi;

        #pragma unroll
        for (int nt = 0; nt < 8; nt++) {
            o[nt][0] *= al_lo; o[nt][1] *= al_lo;
            o[nt][2] *= al_hi; o[nt][3] *= al_hi;
        }

        // ---- O += P V (P from registers; V via ldmatrix.trans) ----
        #pragma unroll
        for (int ks = 0; ks < 4; ks++) {
            uint32_t a0 = plo[2*ks], a1 = phi[2*ks];
            uint32_t a2 = plo[2*ks+1], a3 = phi[2*ks+1];
            int vrow = ks * 16 + vr0;
            uint32_t vbase = vb + (uint32_t)(vrow * 128);
            uint32_t v7 = (uint32_t)(vrow & 7);
            #pragma unroll
            for (int pn = 0; pn < 4; pn++) {
                uint32_t b0, b1, b2, b3;
                ldmx4t(b0, b1, b2, b3, vbase + ((((uint32_t)(pn * 2 + h2)) ^ v7) << 4));
                mma16(o[2*pn][0], o[2*pn][1], o[2*pn][2], o[2*pn][3],
                      a0, a1, a2, a3, b0, b1);
                mma16(o[2*pn+1][0], o[2*pn+1][1], o[2*pn+1][2], o[2*pn+1][3],
                      a0, a1, a2, a3, b2, b3);
            }
        }
    }

    // deferred l reduction across the quad
    l_lo += __shfl_xor_sync(0xffffffffu, l_lo, 1);
    l_lo += __shfl_xor_sync(0xffffffffu, l_lo, 2);
    l_hi += __shfl_xor_sync(0xffffffffu, l_hi, 1);
    l_hi += __shfl_xor_sync(0xffffffffu, l_hi, 2);
    float inv_lo = 1.0f / l_lo;
    float inv_hi = 1.0f / l_hi;

    __half* Og = attn_out + (size_t)(b * SEQ + q0) * D_MODEL + h * HDIM;
    #pragma unroll
    for (int nt = 0; nt < 8; nt++) {
        int col = nt * 8 + 2 * ct;
        *(__half2*)&Og[(size_t)rl * D_MODEL + col] =
            __floats2half2_rn(o[nt][0] * inv_lo, o[nt][1] * inv_lo);
        *(__half2*)&Og[(size_t)(rl + 8) * D_MODEL + col] =
            __floats2half2_rn(o[nt][2] * inv_hi, o[nt][3] * inv_hi);
    }
}

// ===========================================================================
extern "C" void kernel_launch(void* const* d_in, const int* in_sizes, int n_in,
                              void* d_out, int out_size)
{
    const float* x      = (const float*)d_in[0];
    const float* w_qkv  = (const float*)d_in[1];
    const float* w_proj = (const float*)d_in[2];
    float* out = (float*)d_out;

    __half *qkvh, *attnh, *xh, *wqh, *wph;
    cudaGetSymbolAddress((void**)&qkvh,  g_qkvh);
    cudaGetSymbolAddress((void**)&attnh, g_attnh);
    cudaGetSymbolAddress((void**)&xh,    g_xh);
    cudaGetSymbolAddress((void**)&wqh,   g_wqh);
    cudaGetSymbolAddress((void**)&wph,   g_wph);

    cudaFuncSetAttribute(gemm_f16<__half>,
                         cudaFuncAttributeMaxDynamicSharedMemorySize, GEMM_SMEM);
    cudaFuncSetAttribute(gemm_f16<float>,
                         cudaFuncAttributeMaxDynamicSharedMemorySize, GEMM_SMEM);
    cudaFuncSetAttribute(attn_f16,
                         cudaFuncAttributeMaxDynamicSharedMemorySize, ATTN_SMEM);

    // 0) convert inputs/weights to fp16 (one launch)
    int n4 = N4X + N4Q + N4P;
    f2h_all<<<(n4 + 255) / 256, 256>>>(
        (const float4*)x, (const float4*)w_qkv, (const float4*)w_proj,
        (__half2*)xh, (__half2*)wqh, (__half2*)wph);

    // 1) QKV projection; Q columns pre-scaled by (1/8)*log2(e)
    dim3 g1(QKVDIM/128, MROWS/128);
    gemm_f16<__half><<<g1, 256, GEMM_SMEM>>>(xh, wqh, qkvh,
                                             MROWS, QKVDIM, D_MODEL,
                                             D_MODEL, 0.125f * 1.44269504f);

    // 2) causal flash attention (P in registers, exp2 softmax)
    dim3 g2(SEQ/128, NHEAD, BATCH);
    attn_f16<<<g2, 256, ATTN_SMEM>>>(qkvh, attnh);

    // 3) output projection (fp16 in, fp32 out)
    dim3 g3(D_MODEL/128, MROWS/128);
    gemm_f16<float><<<g3, 256, GEMM_SMEM>>>(attnh, wph, out,
                                            MROWS, D_MODEL, D_MODEL,
                                            0, 1.0f);
}

// round 15
// speedup vs baseline: 1.7810x; 1.0333x over previous
#include <cuda_runtime.h>
#include <cuda_fp16.h>
#include <cstdint>

#define D_MODEL 1024
#define NHEAD   16
#define HDIM    64
#define BATCH   2
#define SEQ     2048
#define MROWS   (BATCH*SEQ)       // 4096
#define QKVDIM  (3*D_MODEL)       // 3072

// Scratch (no cudaMalloc allowed)
__device__ __half g_qkvh [BATCH*SEQ*QKVDIM];   // 25 MB
__device__ __half g_attnh[BATCH*SEQ*D_MODEL];  //  8 MB
__device__ __half g_xh   [MROWS*D_MODEL];      //  8 MB
__device__ __half g_wqh  [QKVDIM*D_MODEL];     //  6 MB
__device__ __half g_wph  [D_MODEL*D_MODEL];    //  2 MB

// ---------------------------------------------------------------------------
// helpers
// ---------------------------------------------------------------------------
static __device__ __forceinline__ uint32_t smem_u32(const void* p) {
    uint32_t a;
    asm("{ .reg .u64 t; cvta.to.shared.u64 t, %1; cvt.u32.u64 %0, t; }"
        : "=r"(a) : "l"(p));
    return a;
}
static __device__ __forceinline__ void mma16(
    float& c0, float& c1, float& c2, float& c3,
    uint32_t a0, uint32_t a1, uint32_t a2, uint32_t a3,
    uint32_t b0, uint32_t b1)
{
    asm volatile(
        "mma.sync.aligned.m16n8k16.row.col.f32.f16.f16.f32 "
        "{%0,%1,%2,%3}, {%4,%5,%6,%7}, {%8,%9}, {%0,%1,%2,%3};"
        : "+f"(c0), "+f"(c1), "+f"(c2), "+f"(c3)
        : "r"(a0), "r"(a1), "r"(a2), "r"(a3), "r"(b0), "r"(b1));
}
static __device__ __forceinline__ void ldmx4(
    uint32_t& r0, uint32_t& r1, uint32_t& r2, uint32_t& r3, uint32_t addr)
{
    asm volatile("ldmatrix.sync.aligned.m8n8.x4.shared.b16 {%0,%1,%2,%3}, [%4];"
                 : "=r"(r0), "=r"(r1), "=r"(r2), "=r"(r3) : "r"(addr));
}
static __device__ __forceinline__ void ldmx4t(
    uint32_t& r0, uint32_t& r1, uint32_t& r2, uint32_t& r3, uint32_t addr)
{
    asm volatile("ldmatrix.sync.aligned.m8n8.x4.trans.shared.b16 {%0,%1,%2,%3}, [%4];"
                 : "=r"(r0), "=r"(r1), "=r"(r2), "=r"(r3) : "r"(addr));
}
static __device__ __forceinline__ void cpa16(uint32_t dst, const void* src) {
    asm volatile("cp.async.ca.shared.global [%0], [%1], 16;"
                 :: "r"(dst), "l"(src) : "memory");
}
static __device__ __forceinline__ void cpa_commit() {
    asm volatile("cp.async.commit_group;" ::: "memory");
}
static __device__ __forceinline__ void cpa_wait1() {
    asm volatile("cp.async.wait_group 1;" ::: "memory");
}
static __device__ __forceinline__ void cpa_wait0() {
    asm volatile("cp.async.wait_group 0;" ::: "memory");
}
static __device__ __forceinline__ void st2h(__half* C, size_t off, float a, float b) {
    *(__half2*)(C + off) = __floats2half2_rn(a, b);
}
static __device__ __forceinline__ void st2h(float* C, size_t off, float a, float b) {
    *(float2*)(C + off) = make_float2(a, b);
}
static __device__ __forceinline__ uint32_t packh2(float a, float b) {
    __half2 h = __floats2half2_rn(a, b);
    return *(uint32_t*)&h;
}

// ---------------------------------------------------------------------------
// single-launch f32 -> f16 conversion of x, w_qkv, w_proj
// ---------------------------------------------------------------------------
#define N4X (MROWS*D_MODEL/4)
#define N4Q (QKVDIM*D_MODEL/4)
#define N4P (D_MODEL*D_MODEL/4)
__global__ void __launch_bounds__(256) f2h_all(
    const float4* __restrict__ x, const float4* __restrict__ wq,
    const float4* __restrict__ wp,
    __half2* __restrict__ xh, __half2* __restrict__ wqh, __half2* __restrict__ wph)
{
    int i = blockIdx.x * 256 + threadIdx.x;
    const float4* src; __half2* dst; int j;
    if (i < N4X)                { src = x;  dst = xh;  j = i; }
    else if (i < N4X + N4Q)     { src = wq; dst = wqh; j = i - N4X; }
    else if (i < N4X + N4Q + N4P){ src = wp; dst = wph; j = i - N4X - N4Q; }
    else return;
    float4 v = src[j];
    dst[2 * j]     = __floats2half2_rn(v.x, v.y);
    dst[2 * j + 1] = __floats2half2_rn(v.z, v.w);
}

// ===========================================================================
// fp16 mma GEMM (TN): C[m][n] = sum_k A[m*K+k]*B[n*K+k], fp32 accumulate.
// CTA 128x256, BK=64 halves (128B rows, chunk-swizzle c^(row&7)).
// 256 thr, 8 warps (2m x 4n), warp tile 64x64 -> 128 B ldmatrix per mma
// (was 192 with 64x32). 3-stage cp.async, wait -> sync -> issue ordering.
// ===========================================================================
#define GA_BYTES  16384                 // A stage: 128 rows x 128 B
#define HSTAGE    49152                 // + B stage: 256 rows x 128 B
#define GEMM_SMEM (3*HSTAGE)            // 147456

template<typename OutT>
__global__ void __launch_bounds__(256, 1) gemm_f16(
    const __half* __restrict__ A, const __half* __restrict__ B,
    OutT* __restrict__ C, int M, int N, int K, int q_cols, float qs)
{
    extern __shared__ char smh[];
    const uint32_t sbase = smem_u32(smh);

    const int tid  = threadIdx.x;
    const int wid  = tid >> 5;
    const int lane = tid & 31;
    const int g    = lane >> 2;
    const int ct   = lane & 3;
    const int wm   = wid & 1;       // m slice (x64)
    const int wn   = wid >> 1;      // n slice (x64), 0..3
    const int bm   = blockIdx.y * 128;
    const int bn   = blockIdx.x * 256;
    const float osc = (bn < q_cols) ? qs : 1.0f;

    const int l8 = lane & 7;
    const int h1 = (lane >> 3) & 1;
    const int h2 = lane >> 4;

    uint32_t arow[4], a7[4], brow[4], b7[4];
    #pragma unroll
    for (int mi = 0; mi < 4; mi++) {
        int r = wm * 64 + mi * 16 + l8 + h1 * 8;
        arow[mi] = (uint32_t)(r * 128);
        a7[mi]   = (uint32_t)(r & 7);
    }
    #pragma unroll
    for (int p = 0; p < 4; p++) {
        int r = wn * 64 + p * 16 + l8 + h2 * 8;
        brow[p] = (uint32_t)GA_BYTES + (uint32_t)(r * 128);
        b7[p]   = (uint32_t)(r & 7);
    }

    // cp.async mapping: thread -> row tid>>1, 4 chunks at (tid&1)*4.
    // A: 128 rows (1 pass). B: 256 rows (rows crow and crow+128; same swizzle
    // since 128 = 0 mod 8 -> second row offset = +16384 bytes).
    const int crow = tid >> 1;
    const int cc0  = (tid & 1) * 4;
    const __half* Ag  = A + (size_t)(bm + crow) * K;
    const __half* Bg  = B + (size_t)(bn + crow) * K;
    const __half* Bg2 = B + (size_t)(bn + crow + 128) * K;
    uint32_t dwa[4], dwb[4];
    #pragma unroll
    for (int i = 0; i < 4; i++) {
        uint32_t sw = (uint32_t)(((cc0 + i) ^ (crow & 7)) * 16);
        dwa[i] = (uint32_t)(crow * 128) + sw;
        dwb[i] = (uint32_t)GA_BYTES + (uint32_t)(crow * 128) + sw;
    }

    const int nkt = K / 64;

    float acc[4][8][4];
    #pragma unroll
    for (int i = 0; i < 4; i++)
        #pragma unroll
        for (int j = 0; j < 8; j++)
            #pragma unroll
            for (int e = 0; e < 4; e++) acc[i][j][e] = 0.f;

    // prologue: stages 0,1
    #pragma unroll
    for (int s = 0; s < 2; s++) {
        uint32_t st = sbase + (uint32_t)s * HSTAGE;
        #pragma unroll
        for (int i = 0; i < 4; i++) {
            cpa16(st + dwa[i],          Ag  + s * 64 + (cc0 + i) * 8);
            cpa16(st + dwb[i],          Bg  + s * 64 + (cc0 + i) * 8);
            cpa16(st + dwb[i] + 16384u, Bg2 + s * 64 + (cc0 + i) * 8);
        }
        cpa_commit();
    }

    int sc = 0;
    for (int kt = 0; kt < nkt; kt++) {
        cpa_wait1();       // stage sc complete (own groups)
        __syncthreads();   // cross-thread visibility + readers of old stage done

        if (kt + 2 < nkt) {
            int sn = sc + 2; if (sn >= 3) sn -= 3;
            uint32_t st = sbase + (uint32_t)sn * HSTAGE;
            #pragma unroll
            for (int i = 0; i < 4; i++) {
                cpa16(st + dwa[i],          Ag  + (kt + 2) * 64 + (cc0 + i) * 8);
                cpa16(st + dwb[i],          Bg  + (kt + 2) * 64 + (cc0 + i) * 8);
                cpa16(st + dwb[i] + 16384u, Bg2 + (kt + 2) * 64 + (cc0 + i) * 8);
            }
        }
        cpa_commit();      // uniform group counting (possibly empty)

        const uint32_t cbase = sbase + (uint32_t)sc * HSTAGE;
        #pragma unroll
        for (int ks = 0; ks < 4; ks++) {
            uint32_t a[4][4], bb[4][4];
            #pragma unroll
            for (int mi = 0; mi < 4; mi++)
                ldmx4(a[mi][0], a[mi][1], a[mi][2], a[mi][3],
                      cbase + arow[mi] + ((((uint32_t)(ks * 2 + h2)) ^ a7[mi]) << 4));
            #pragma unroll
            for (int p = 0; p < 4; p++)
                ldmx4(bb[p][0], bb[p][1], bb[p][2], bb[p][3],
                      cbase + brow[p] + ((((uint32_t)(ks * 2 + h1)) ^ b7[p]) << 4));
            #pragma unroll
            for (int mi = 0; mi < 4; mi++)
                #pragma unroll
                for (int nt = 0; nt < 8; nt++)
                    mma16(acc[mi][nt][0], acc[mi][nt][1], acc[mi][nt][2], acc[mi][nt][3],
                          a[mi][0], a[mi][1], a[mi][2], a[mi][3],
                          bb[nt >> 1][(nt & 1) * 2], bb[nt >> 1][(nt & 1) * 2 + 1]);
        }
        sc++; if (sc >= 3) sc -= 3;
    }

    #pragma unroll
    for (int mi = 0; mi < 4; mi++) {
        int r0 = bm + wm * 64 + mi * 16 + g;
        #pragma unroll
        for (int nt = 0; nt < 8; nt++) {
            int c0 = bn + wn * 64 + nt * 8 + 2 * ct;
            st2h(C, (size_t)r0 * N + c0,
                 acc[mi][nt][0] * osc, acc[mi][nt][1] * osc);
            st2h(C, (size_t)(r0 + 8) * N + c0,
                 acc[mi][nt][2] * osc, acc[mi][nt][3] * osc);
        }
    }
}

// ===========================================================================
// Flash attention, fp16 mma, P in registers (FA2), exp2-domain softmax,
// 2-stage cp.async K/V pipeline (R11/R14 ordering). Unchanged.
// ===========================================================================
#define AQ_OFF 0
#define AK_OFF 16384
#define AV_OFF 32768
#define ATTN_SMEM 49152

__global__ void __launch_bounds__(256, 2) attn_f16(
    const __half* __restrict__ qkv, __half* __restrict__ attn_out)
{
    extern __shared__ char smh[];
    const uint32_t sb = smem_u32(smh);

    const int qt  = (int)gridDim.x - 1 - (int)blockIdx.x;  // heavy blocks first
    const int h   = blockIdx.y;
    const int b   = blockIdx.z;
    const int tid = threadIdx.x;
    const int wid = tid >> 5;
    const int lane = tid & 31;
    const int g   = lane >> 2;
    const int ct  = lane & 3;
    const int q0  = qt * 128;
    const int rl  = wid * 16 + g;

    const int l8 = lane & 7;
    const int h1 = (lane >> 3) & 1;
    const int h2 = lane >> 4;

    const int arow = wid * 16 + l8 + h1 * 8;
    const uint32_t qbase = sb + AQ_OFF + (uint32_t)(arow * 128);
    const uint32_t a7 = (uint32_t)(arow & 7);
    uint32_t krow[4], k7[4];
    #pragma unroll
    for (int p = 0; p < 4; p++) {
        int r = p * 16 + l8 + h2 * 8;
        krow[p] = (uint32_t)(r * 128);
        k7[p]   = (uint32_t)(r & 7);
    }
    const int vr0 = l8 + h1 * 8;

    const size_t rs = QKVDIM;
    const __half* Qg = qkv + (size_t)b * SEQ * rs + h * HDIM;
    const __half* Kg = Qg + D_MODEL;
    const __half* Vg = Qg + 2 * D_MODEL;

    const int krr0 = tid >> 3;
    const int kc   = tid & 7;
    const uint32_t ksw0 = (uint32_t)(krr0 * 128 + ((kc ^ (krr0 & 7)) * 16));
    const int krr1 = krr0 + 32;
    const uint32_t ksw1 = (uint32_t)(krr1 * 128 + ((kc ^ (krr1 & 7)) * 16));

    // load Q tile (once)
    #pragma unroll
    for (int it = 0; it < 4; it++) {
        int idx = tid + it * 256;
        int rr  = idx >> 3;
        int c   = idx & 7;
        uint4 v = *(const uint4*)(Qg + (size_t)(q0 + rr) * rs + c * 8);
        *(uint4*)(smh + AQ_OFF + rr * 128 + ((c ^ (rr & 7)) * 16)) = v;
    }

    const int nkt = 2 * qt + 2;

    // prologue: kt=0 K/V into stage 0
    cpa16(sb + AK_OFF + ksw0, Kg + (size_t)krr0 * rs + kc * 8);
    cpa16(sb + AK_OFF + ksw1, Kg + (size_t)krr1 * rs + kc * 8);
    cpa16(sb + AV_OFF + ksw0, Vg + (size_t)krr0 * rs + kc * 8);
    cpa16(sb + AV_OFF + ksw1, Vg + (size_t)krr1 * rs + kc * 8);
    cpa_commit();

    float m_lo = -1e30f, m_hi = -1e30f, l_lo = 0.f, l_hi = 0.f;
    float o[8][4];
    #pragma unroll
    for (int nt = 0; nt < 8; nt++)
        #pragma unroll
        for (int e = 0; e < 4; e++) o[nt][e] = 0.f;

    for (int kt = 0; kt < nkt; kt++) {
        cpa_wait0();       // own groups complete
        __syncthreads();   // cross-thread visibility + old-stage readers done

        if (kt + 1 < nkt) {
            const int k1 = (kt + 1) * 64;
            const uint32_t so = (uint32_t)((kt + 1) & 1) * 8192u;
            cpa16(sb + AK_OFF + so + ksw0, Kg + (size_t)(k1 + krr0) * rs + kc * 8);
            cpa16(sb + AK_OFF + so + ksw1, Kg + (size_t)(k1 + krr1) * rs + kc * 8);
            cpa16(sb + AV_OFF + so + ksw0, Vg + (size_t)(k1 + krr0) * rs + kc * 8);
            cpa16(sb + AV_OFF + so + ksw1, Vg + (size_t)(k1 + krr1) * rs + kc * 8);
            cpa_commit();
        }

        const int k0 = kt * 64;
        if (k0 > q0 + wid * 16 + 15) continue;   // fully above diagonal

        const uint32_t kb = sb + AK_OFF + (uint32_t)(kt & 1) * 8192u;
        const uint32_t vb = sb + AV_OFF + (uint32_t)(kt & 1) * 8192u;

        // ---- S = Q K^T (S in log2 units) ----
        float s[8][4];
        #pragma unroll
        for (int nt = 0; nt < 8; nt++)
            #pragma unroll
            for (int e = 0; e < 4; e++) s[nt][e] = 0.f;

        #pragma unroll
        for (int ks = 0; ks < 4; ks++) {
            uint32_t a0, a1, a2, a3;
            ldmx4(a0, a1, a2, a3, qbase + ((((uint32_t)(ks * 2 + h2)) ^ a7) << 4));
            #pragma unroll
            for (int p = 0; p < 4; p++) {
                uint32_t b0, b1, b2, b3;
                ldmx4(b0, b1, b2, b3, kb + krow[p] + ((((uint32_t)(ks * 2 + h1)) ^ k7[p]) << 4));
                mma16(s[2*p][0], s[2*p][1], s[2*p][2], s[2*p][3],
                      a0, a1, a2, a3, b0, b1);
                mma16(s[2*p+1][0], s[2*p+1][1], s[2*p+1][2], s[2*p+1][3],
                      a0, a1, a2, a3, b2, b3);
            }
        }

        // ---- causal mask ----
        const int rglo = q0 + rl;
        const int rghi = rglo + 8;
        if (k0 + 63 > rglo) {
            #pragma unroll
            for (int nt = 0; nt < 8; nt++) {
                int key = k0 + nt * 8 + 2 * ct;
                if (key     > rglo) s[nt][0] = -1e30f;
                if (key + 1 > rglo) s[nt][1] = -1e30f;
                if (key     > rghi) s[nt][2] = -1e30f;
                if (key + 1 > rghi) s[nt][3] = -1e30f;
            }
        }

        // ---- online softmax (base 2; quad reduce for m) ----
        float tlo = -1e30f, thi = -1e30f;
        #pragma unroll
        for (int nt = 0; nt < 8; nt++) {
            tlo = fmaxf(tlo, fmaxf(s[nt][0], s[nt][1]));
            thi = fmaxf(thi, fmaxf(s[nt][2], s[nt][3]));
        }
        tlo = fmaxf(tlo, __shfl_xor_sync(0xffffffffu, tlo, 1));
        tlo = fmaxf(tlo, __shfl_xor_sync(0xffffffffu, tlo, 2));
        thi = fmaxf(thi, __shfl_xor_sync(0xffffffffu, thi, 1));
        thi = fmaxf(thi, __shfl_xor_sync(0xffffffffu, thi, 2));

        float mn_lo = fmaxf(m_lo, tlo);
        float mn_hi = fmaxf(m_hi, thi);
        float al_lo = exp2f(m_lo - mn_lo);
        float al_hi = exp2f(m_hi - mn_hi);
        m_lo = mn_lo; m_hi = mn_hi;

        uint32_t plo[8], phi[8];
        float ps_lo = 0.f, ps_hi = 0.f;
        #pragma unroll
        for (int nt = 0; nt < 8; nt++) {
            float p0 = exp2f(s[nt][0] - mn_lo);
            float p1 = exp2f(s[nt][1] - mn_lo);
            float p2 = exp2f(s[nt][2] - mn_hi);
            float p3 = exp2f(s[nt][3] - mn_hi);
            ps_lo += p0 + p1;
            ps_hi += p2 + p3;
            plo[nt] = packh2(p0, p1);
            phi[nt] = packh2(p2, p3);
        }
        l_lo = l_lo * al_lo + ps_lo;
        l_hi = l_hi * al_hi + ps_hi;

        #pragma unroll
        for (int nt = 0; nt < 8; nt++) {
            o[nt][0] *= al_lo; o[nt][1] *= al_lo;
            o[nt][2] *= al_hi; o[nt][3] *= al_hi;
        }

        // ---- O += P V (P from registers; V via ldmatrix.trans) ----
        #pragma unroll
        for (int ks = 0; ks < 4; ks++) {
            uint32_t a0 = plo[2*ks], a1 = phi[2*ks];
            uint32_t a2 = plo[2*ks+1], a3 = phi[2*ks+1];
            int vrow = ks * 16 + vr0;
            uint32_t vbase = vb + (uint32_t)(vrow * 128);
            uint32_t v7 = (uint32_t)(vrow & 7);
            #pragma unroll
            for (int pn = 0; pn < 4; pn++) {
                uint32_t b0, b1, b2, b3;
                ldmx4t(b0, b1, b2, b3, vbase + ((((uint32_t)(pn * 2 + h2)) ^ v7) << 4));
                mma16(o[2*pn][0], o[2*pn][1], o[2*pn][2], o[2*pn][3],
                      a0, a1, a2, a3, b0, b1);
                mma16(o[2*pn+1][0], o[2*pn+1][1], o[2*pn+1][2], o[2*pn+1][3],
                      a0, a1, a2, a3, b2, b3);
            }
        }
    }

    // deferred l reduction across the quad
    l_lo += __shfl_xor_sync(0xffffffffu, l_lo, 1);
    l_lo += __shfl_xor_sync(0xffffffffu, l_lo, 2);
    l_hi += __shfl_xor_sync(0xffffffffu, l_hi, 1);
    l_hi += __shfl_xor_sync(0xffffffffu, l_hi, 2);
    float inv_lo = 1.0f / l_lo;
    float inv_hi = 1.0f / l_hi;

    __half* Og = attn_out + (size_t)(b * SEQ + q0) * D_MODEL + h * HDIM;
    #pragma unroll
    for (int nt = 0; nt < 8; nt++) {
        int col = nt * 8 + 2 * ct;
        *(__half2*)&Og[(size_t)rl * D_MODEL + col] =
            __floats2half2_rn(o[nt][0] * inv_lo, o[nt][1] * inv_lo);
        *(__half2*)&Og[(size_t)(rl + 8) * D_MODEL + col] =
            __floats2half2_rn(o[nt][2] * inv_hi, o[nt][3] * inv_hi);
    }
}

// ===========================================================================
extern "C" void kernel_launch(void* const* d_in, const int* in_sizes, int n_in,
                              void* d_out, int out_size)
{
    const float* x      = (const float*)d_in[0];
    const float* w_qkv  = (const float*)d_in[1];
    const float* w_proj = (const float*)d_in[2];
    float* out = (float*)d_out;

    __half *qkvh, *attnh, *xh, *wqh, *wph;
    cudaGetSymbolAddress((void**)&qkvh,  g_qkvh);
    cudaGetSymbolAddress((void**)&attnh, g_attnh);
    cudaGetSymbolAddress((void**)&xh,    g_xh);
    cudaGetSymbolAddress((void**)&wqh,   g_wqh);
    cudaGetSymbolAddress((void**)&wph,   g_wph);

    cudaFuncSetAttribute(gemm_f16<__half>,
                         cudaFuncAttributeMaxDynamicSharedMemorySize, GEMM_SMEM);
    cudaFuncSetAttribute(gemm_f16<float>,
                         cudaFuncAttributeMaxDynamicSharedMemorySize, GEMM_SMEM);
    cudaFuncSetAttribute(attn_f16,
                         cudaFuncAttributeMaxDynamicSharedMemorySize, ATTN_SMEM);

    // 0) convert inputs/weights to fp16 (one launch)
    int n4 = N4X + N4Q + N4P;
    f2h_all<<<(n4 + 255) / 256, 256>>>(
        (const float4*)x, (const float4*)w_qkv, (const float4*)w_proj,
        (__half2*)xh, (__half2*)wqh, (__half2*)wph);

    // 1) QKV projection (CTA 128x256); Q columns pre-scaled by (1/8)*log2(e)
    dim3 g1(QKVDIM/256, MROWS/128);
    gemm_f16<__half><<<g1, 256, GEMM_SMEM>>>(xh, wqh, qkvh,
                                             MROWS, QKVDIM, D_MODEL,
                                             D_MODEL, 0.125f * 1.44269504f);

    // 2) causal flash attention (P in registers, exp2 softmax)
    dim3 g2(SEQ/128, NHEAD, BATCH);
    attn_f16<<<g2, 256, ATTN_SMEM>>>(qkvh, attnh);

    // 3) output projection (fp16 in, fp32 out)
    dim3 g3(D_MODEL/256, MROWS/128);
    gemm_f16<float><<<g3, 256, GEMM_SMEM>>>(attnh, wph, out,
                                            MROWS, D_MODEL, D_MODEL,
                                            0, 1.0f);
}